// round 3
// baseline (speedup 1.0000x reference)
#include <cuda_runtime.h>
#include <cuda_bf16.h>
#include <cstdint>

// Problem constants
#define BATCH 2
#define LSEQ  2048
#define HID   2048
#define NH    16
#define NKV   8
#define HD    128
#define NIMG  1024
#define MROWS (BATCH*LSEQ)   // 4096

// ---------------- scratch (device globals; no allocation allowed) ----------
__device__ float g_q [(size_t)BATCH*LSEQ*NH *HD];
__device__ float g_k [(size_t)BATCH*LSEQ*NKV*HD];
__device__ float g_v [(size_t)BATCH*LSEQ*NKV*HD];

__device__ __nv_bfloat16 g_xhi [(size_t)MROWS*HID];
__device__ __nv_bfloat16 g_xlo [(size_t)MROWS*HID];
__device__ __nv_bfloat16 g_wqhi[(size_t)NH*HD*HID];
__device__ __nv_bfloat16 g_wqlo[(size_t)NH*HD*HID];
__device__ __nv_bfloat16 g_wkhi[(size_t)NKV*HD*HID];
__device__ __nv_bfloat16 g_wklo[(size_t)NKV*HD*HID];
__device__ __nv_bfloat16 g_wvhi[(size_t)NKV*HD*HID];
__device__ __nv_bfloat16 g_wvlo[(size_t)NKV*HD*HID];
__device__ __nv_bfloat16 g_wohi[(size_t)HID*NH*HD];
__device__ __nv_bfloat16 g_wolo[(size_t)HID*NH*HD];
__device__ __nv_bfloat16 g_aohi[(size_t)MROWS*NH*HD];
__device__ __nv_bfloat16 g_aolo[(size_t)MROWS*NH*HD];

// ---------------- PTX helpers (baseline ISA only: sm_80-era) ---------------
__device__ __forceinline__ uint32_t smem_u32(const void* p) {
    uint32_t a;
    asm("{ .reg .u64 t; cvta.to.shared.u64 t, %1; cvt.u32.u64 %0, t; }"
        : "=r"(a) : "l"(p));
    return a;
}

#define CP_ASYNC16(sm, gp) \
    asm volatile("cp.async.ca.shared.global [%0], [%1], 16;" :: "r"(sm), "l"(gp) : "memory")
#define CP_COMMIT() asm volatile("cp.async.commit_group;" ::: "memory")
#define CP_WAIT0()  asm volatile("cp.async.wait_group 0;" ::: "memory")

#define LDMATRIX_X4(r0, r1, r2, r3, addr) \
    asm volatile("ldmatrix.sync.aligned.m8n8.x4.shared.b16 {%0,%1,%2,%3}, [%4];" \
        : "=r"(r0), "=r"(r1), "=r"(r2), "=r"(r3) : "r"(addr))

#define MMA_BF16(d, a, b0, b1) \
    asm volatile("mma.sync.aligned.m16n8k16.row.col.f32.bf16.bf16.f32 " \
        "{%0,%1,%2,%3}, {%4,%5,%6,%7}, {%8,%9}, {%0,%1,%2,%3};" \
        : "+f"((d)[0]), "+f"((d)[1]), "+f"((d)[2]), "+f"((d)[3]) \
        : "r"((a)[0]), "r"((a)[1]), "r"((a)[2]), "r"((a)[3]), "r"(b0), "r"(b1))

// ---------------- fp32 -> bf16 hi/lo split ----------------------------------
__global__ __launch_bounds__(256) void split_bf16(const float* __restrict__ src,
                                                  __nv_bfloat16* __restrict__ hi,
                                                  __nv_bfloat16* __restrict__ lo,
                                                  int n /* multiple of 4 */)
{
    int i = (blockIdx.x * 256 + threadIdx.x) * 4;
    if (i >= n) return;
    float4 v = *(const float4*)(src + i);
    __nv_bfloat16 h0 = __float2bfloat16(v.x), h1 = __float2bfloat16(v.y);
    __nv_bfloat16 h2 = __float2bfloat16(v.z), h3 = __float2bfloat16(v.w);
    __nv_bfloat16 l0 = __float2bfloat16(v.x - __bfloat162float(h0));
    __nv_bfloat16 l1 = __float2bfloat16(v.y - __bfloat162float(h1));
    __nv_bfloat16 l2 = __float2bfloat16(v.z - __bfloat162float(h2));
    __nv_bfloat16 l3 = __float2bfloat16(v.w - __bfloat162float(h3));
    __nv_bfloat162 hp0 = __nv_bfloat162(h0, h1), hp1 = __nv_bfloat162(h2, h3);
    __nv_bfloat162 lp0 = __nv_bfloat162(l0, l1), lp1 = __nv_bfloat162(l2, l3);
    uint2 hv, lv;
    hv.x = *(uint32_t*)&hp0; hv.y = *(uint32_t*)&hp1;
    lv.x = *(uint32_t*)&lp0; lv.y = *(uint32_t*)&lp1;
    *(uint2*)(hi + i) = hv;
    *(uint2*)(lo + i) = lv;
}

// ---------------- bf16 split GEMM via mma.sync ------------------------------
// C[m,n] = sum_k (Ahi+Alo)[m,k]*(Bhi+Blo)[n,k], Alo*Blo dropped.
// CTA: 128x128 tile. 8 warps -> each 64x32. BK=32, cp.async double buffer.
#define BK      32
#define ASTR    40                       // halves per smem row (pad 32->40)
#define TILEB   (128*ASTR*2)             // bytes per tile buffer

__global__ __launch_bounds__(256) void gemm_mma_split(
        const __nv_bfloat16* __restrict__ Ahi, const __nv_bfloat16* __restrict__ Alo,
        const __nv_bfloat16* __restrict__ Bhi, const __nv_bfloat16* __restrict__ Blo,
        float* __restrict__ C, int M, int N, int K)
{
    __shared__ __nv_bfloat16 As[2][128*ASTR];
    __shared__ __nv_bfloat16 Bs[2][128*ASTR];

    const int tid  = threadIdx.x;
    const int wid  = tid >> 5, lane = tid & 31;
    const int wm   = wid >> 2;          // 0..1  (m block of 64)
    const int wn   = wid & 3;           // 0..3  (n block of 32)
    const int mb   = blockIdx.y * 128;
    const int nb   = blockIdx.x * 128;

    const __nv_bfloat16* Aps[3] = {Ahi, Ahi, Alo};
    const __nv_bfloat16* Bps[3] = {Bhi, Blo, Bhi};

    const uint32_t sA = smem_u32(As);
    const uint32_t sB = smem_u32(Bs);

    // g2s coords: thread handles rows (tid>>2) and (tid>>2)+64, col (tid&3)*8
    const int lrow = tid >> 2;
    const int lcol = (tid & 3) * 8;
    const uint32_t sAo = sA + (uint32_t)(lrow * ASTR + lcol) * 2;
    const uint32_t sBo = sB + (uint32_t)(lrow * ASTR + lcol) * 2;

    const int kchunks = K / BK;
    const int total   = 3 * kchunks;

    float acc[4][4][4];
#pragma unroll
    for (int i = 0; i < 4; i++)
#pragma unroll
        for (int j = 0; j < 4; j++)
#pragma unroll
            for (int r = 0; r < 4; r++) acc[i][j][r] = 0.f;

    // ldmatrix lane addressing
    const int fr = lane & 15;            // row within 16
    const int fc = (lane >> 4) * 8;      // k-half select (0/8)
    const uint32_t aF = sA + (uint32_t)((wm*64 + fr) * ASTR + fc) * 2;
    const uint32_t bF = sB + (uint32_t)((wn*32 + fr) * ASTR + fc) * 2;

    // prefetch chunk 0 into buf 0
    {
        const __nv_bfloat16* Ab = Aps[0] + (size_t)mb * K;
        const __nv_bfloat16* Bb = Bps[0] + (size_t)nb * K;
#pragma unroll
        for (int i = 0; i < 2; i++) {
            int row = lrow + i * 64;
            CP_ASYNC16(sAo + i * 64 * ASTR * 2, Ab + (size_t)row * K + lcol);
            CP_ASYNC16(sBo + i * 64 * ASTR * 2, Bb + (size_t)row * K + lcol);
        }
        CP_COMMIT();
    }
    CP_WAIT0();
    __syncthreads();

    int buf = 0;
    for (int c = 0; c < total; c++) {
        if (c + 1 < total) {
            int cn = c + 1;
            int pass = cn / kchunks, k0 = (cn % kchunks) * BK;
            const __nv_bfloat16* Ab = Aps[pass] + (size_t)mb * K + k0;
            const __nv_bfloat16* Bb = Bps[pass] + (size_t)nb * K + k0;
            uint32_t dstA = sAo + (buf ^ 1) * TILEB;
            uint32_t dstB = sBo + (buf ^ 1) * TILEB;
#pragma unroll
            for (int i = 0; i < 2; i++) {
                int row = lrow + i * 64;
                CP_ASYNC16(dstA + i * 64 * ASTR * 2, Ab + (size_t)row * K + lcol);
                CP_ASYNC16(dstB + i * 64 * ASTR * 2, Bb + (size_t)row * K + lcol);
            }
            CP_COMMIT();
        }

        // compute on buf
        const uint32_t aBase = aF + buf * TILEB;
        const uint32_t bBase = bF + buf * TILEB;
#pragma unroll
        for (int ks = 0; ks < 2; ks++) {
            uint32_t a[4][4], bfr[2][4];
#pragma unroll
            for (int mt = 0; mt < 4; mt++)
                LDMATRIX_X4(a[mt][0], a[mt][1], a[mt][2], a[mt][3],
                            aBase + (uint32_t)(mt*16*ASTR + ks*16) * 2);
#pragma unroll
            for (int nt2 = 0; nt2 < 2; nt2++)
                LDMATRIX_X4(bfr[nt2][0], bfr[nt2][1], bfr[nt2][2], bfr[nt2][3],
                            bBase + (uint32_t)(nt2*16*ASTR + ks*16) * 2);
#pragma unroll
            for (int mt = 0; mt < 4; mt++)
#pragma unroll
                for (int nt = 0; nt < 4; nt++) {
                    int n2 = nt >> 1, hi = nt & 1;
                    MMA_BF16(acc[mt][nt], a[mt], bfr[n2][hi], bfr[n2][hi + 2]);
                }
        }

        CP_WAIT0();
        __syncthreads();
        buf ^= 1;
    }

    // epilogue: D m16n8 fragment layout
    const int drow = lane >> 2;
    const int dcol = (lane & 3) * 2;
#pragma unroll
    for (int mt = 0; mt < 4; mt++) {
#pragma unroll
        for (int nt = 0; nt < 4; nt++) {
            int r0 = mb + wm*64 + mt*16 + drow;
            int cc = nb + wn*32 + nt*8 + dcol;
            *(float2*)(C + (size_t)r0 * N + cc) =
                make_float2(acc[mt][nt][0], acc[mt][nt][1]);
            *(float2*)(C + (size_t)(r0 + 8) * N + cc) =
                make_float2(acc[mt][nt][2], acc[mt][nt][3]);
        }
    }
}

// ---------------- fused RMSNorm + RoPE (q and k heads) ---------------------
__global__ __launch_bounds__(128) void rmsnorm_rope_kernel(
        float* __restrict__ qb, float* __restrict__ kb,
        const float* __restrict__ cosb, const float* __restrict__ sinb,
        const float* __restrict__ qw, const float* __restrict__ kw)
{
    const int idx  = blockIdx.x;
    const int head = idx % (NH + NKV);
    const int bl   = idx / (NH + NKV);
    const int d    = threadIdx.x;

    float* vec; const float* w;
    if (head < NH) { vec = qb + ((size_t)bl*NH  + head)      * HD; w = qw; }
    else           { vec = kb + ((size_t)bl*NKV + (head-NH)) * HD; w = kw; }

    float val = vec[d];
    float ss  = val * val;
#pragma unroll
    for (int o = 16; o > 0; o >>= 1) ss += __shfl_xor_sync(0xffffffffu, ss, o);
    __shared__ float wsum[4];
    if ((d & 31) == 0) wsum[d >> 5] = ss;
    __syncthreads();
    float tot = wsum[0] + wsum[1] + wsum[2] + wsum[3];
    float r   = rsqrtf(tot * (1.0f/HD) + 1e-6f);
    float nv  = val * r * w[d];

    __shared__ float sv[HD];
    sv[d] = nv;
    __syncthreads();

    const float* cp = cosb + (size_t)bl * HD;
    const float* sp = sinb + (size_t)bl * HD;
    float outv;
    if (d < 64) outv = nv * cp[d]    - sv[d+64] * sp[d];
    else        outv = nv * cp[d-64] + sv[d-64] * sp[d-64];
    vec[d] = outv;
}

// ---------------- flash attention, fp32, hybrid mask -----------------------
// 64 queries/block, 256 threads; 4 lanes/query each own 32 of 128 dims.
// Dim traversal rotated by sub*8 -> conflict-free smem reads.
__global__ __launch_bounds__(256, 2) void attn_kernel(
        const float* __restrict__ Q, const float* __restrict__ Kb,
        const float* __restrict__ Vb,
        __nv_bfloat16* __restrict__ Ohi, __nv_bfloat16* __restrict__ Olo)
{
    __shared__ float Ks[32][HD];
    __shared__ float Vs[32][HD];

    const int tid = threadIdx.x;
    const int qi  = tid >> 2;
    const int sub = tid & 3;
    const int rot = sub * 8;
    const int b   = blockIdx.z;
    const int h   = blockIdx.y;
    const int q0  = blockIdx.x * 64;
    const int kvh = h >> 1;
    const int qrow = q0 + qi;

    const float* qp = Q + (((size_t)b*LSEQ + qrow)*NH + h)*HD + sub*32;
    float qreg[32];
#pragma unroll
    for (int d = 0; d < 32; d++) qreg[d] = qp[d];

    float m = -1e30f, lsum = 0.f;
    float acc[32];
#pragma unroll
    for (int d = 0; d < 32; d++) acc[d] = 0.f;

    const float scale = 0.08838834764831844f;
    const int nk = (q0 >= NIMG) ? (q0/32 + 2) : (LSEQ/32);

    for (int t = 0; t < nk; t++) {
        const int k0 = t * 32;
        const size_t kbase = (((size_t)b*LSEQ + k0)*NKV + kvh)*HD;
#pragma unroll
        for (int i = 0; i < 4; i++) {
            int idx = tid + i*256;
            int row = idx >> 5, c = (idx & 31) << 2;
            size_t g = kbase + (size_t)row*NKV*HD + c;
            *(float4*)&Ks[row][c] = *(const float4*)(Kb + g);
            *(float4*)&Vs[row][c] = *(const float4*)(Vb + g);
        }
        __syncthreads();

        float sloc[8];
        float smax = -1e30f;
#pragma unroll
        for (int kk = 0; kk < 32; kk++) {
            float p = 0.f;
            const float* kr = &Ks[kk][sub*32];
#pragma unroll
            for (int d = 0; d < 32; d++) {
                int j = (d + rot) & 31;
                p += qreg[j] * kr[j];
            }
            p += __shfl_xor_sync(0xffffffffu, p, 1);
            p += __shfl_xor_sync(0xffffffffu, p, 2);
            p *= scale;
            int kc = k0 + kk;
            if (!((kc <= qrow) || (qrow < NIMG))) p = -1e30f;
            if ((kk & 3) == sub) sloc[kk >> 2] = p;
            smax = fmaxf(smax, p);
        }

        float newm  = fmaxf(m, smax);
        float alpha = __expf(fmaxf(m - newm, -80.f));
        lsum *= alpha;
#pragma unroll
        for (int d = 0; d < 32; d++) acc[d] *= alpha;

#pragma unroll
        for (int kk = 0; kk < 32; kk++) {
            float svv = __shfl_sync(0xffffffffu, sloc[kk >> 2], kk & 3, 4);
            float p   = __expf(fmaxf(svv - newm, -80.f));
            lsum += p;
            const float* vr = &Vs[kk][sub*32];
#pragma unroll
            for (int d = 0; d < 32; d++) {
                int j = (d + rot) & 31;
                acc[j] += p * vr[j];
            }
        }
        m = newm;
        __syncthreads();
    }

    float inv = 1.f / lsum;
    size_t obase = (((size_t)b*LSEQ + qrow)*NH + h)*HD + sub*32;
#pragma unroll
    for (int d = 0; d < 32; d++) {
        float o = acc[d] * inv;
        __nv_bfloat16 hv = __float2bfloat16(o);
        __nv_bfloat16 lv = __float2bfloat16(o - __bfloat162float(hv));
        Ohi[obase + d] = hv;
        Olo[obase + d] = lv;
    }
}

// ---------------- launch ----------------------------------------------------
extern "C" void kernel_launch(void* const* d_in, const int* in_sizes, int n_in,
                              void* d_out, int out_size)
{
    const float* x    = (const float*)d_in[0];
    const float* cosb = (const float*)d_in[1];
    const float* sinb = (const float*)d_in[2];
    // d_in[3] = attention_mask (recomputed analytically, unused)
    const float* Wq   = (const float*)d_in[4];
    const float* Wk   = (const float*)d_in[5];
    const float* Wv   = (const float*)d_in[6];
    const float* Wo   = (const float*)d_in[7];
    const float* qw   = (const float*)d_in[8];
    const float* kw   = (const float*)d_in[9];
    float* out = (float*)d_out;

    float *gq, *gk, *gv;
    __nv_bfloat16 *xhi, *xlo, *wqhi, *wqlo, *wkhi, *wklo, *wvhi, *wvlo;
    __nv_bfloat16 *wohi, *wolo, *aohi, *aolo;
    cudaGetSymbolAddress((void**)&gq,   g_q);
    cudaGetSymbolAddress((void**)&gk,   g_k);
    cudaGetSymbolAddress((void**)&gv,   g_v);
    cudaGetSymbolAddress((void**)&xhi,  g_xhi);
    cudaGetSymbolAddress((void**)&xlo,  g_xlo);
    cudaGetSymbolAddress((void**)&wqhi, g_wqhi);
    cudaGetSymbolAddress((void**)&wqlo, g_wqlo);
    cudaGetSymbolAddress((void**)&wkhi, g_wkhi);
    cudaGetSymbolAddress((void**)&wklo, g_wklo);
    cudaGetSymbolAddress((void**)&wvhi, g_wvhi);
    cudaGetSymbolAddress((void**)&wvlo, g_wvlo);
    cudaGetSymbolAddress((void**)&wohi, g_wohi);
    cudaGetSymbolAddress((void**)&wolo, g_wolo);
    cudaGetSymbolAddress((void**)&aohi, g_aohi);
    cudaGetSymbolAddress((void**)&aolo, g_aolo);

    // bf16 hi/lo splits
    const int nx  = MROWS * HID;
    const int nwq = NH  * HD * HID;
    const int nwk = NKV * HD * HID;
    const int nwo = HID * NH * HD;
    split_bf16<<<nx  / 1024, 256>>>(x,  xhi,  xlo,  nx);
    split_bf16<<<nwq / 1024, 256>>>(Wq, wqhi, wqlo, nwq);
    split_bf16<<<nwk / 1024, 256>>>(Wk, wkhi, wklo, nwk);
    split_bf16<<<nwk / 1024, 256>>>(Wv, wvhi, wvlo, nwk);
    split_bf16<<<nwo / 1024, 256>>>(Wo, wohi, wolo, nwo);

    // QKV projections on tensor cores (mma.sync bf16, split)
    gemm_mma_split<<<dim3(NH*HD/128,  MROWS/128), 256>>>(
        xhi, xlo, wqhi, wqlo, gq, MROWS, NH*HD,  HID);
    gemm_mma_split<<<dim3(NKV*HD/128, MROWS/128), 256>>>(
        xhi, xlo, wkhi, wklo, gk, MROWS, NKV*HD, HID);
    gemm_mma_split<<<dim3(NKV*HD/128, MROWS/128), 256>>>(
        xhi, xlo, wvhi, wvlo, gv, MROWS, NKV*HD, HID);

    // RMSNorm + RoPE
    rmsnorm_rope_kernel<<<BATCH*LSEQ*(NH+NKV), 128>>>(gq, gk, cosb, sinb, qw, kw);

    // Attention (writes bf16 hi/lo directly)
    attn_kernel<<<dim3(LSEQ/64, NH, BATCH), 256>>>(gq, gk, gv, aohi, aolo);

    // Output projection
    gemm_mma_split<<<dim3(HID/128, MROWS/128), 256>>>(
        aohi, aolo, wohi, wolo, out, MROWS, HID, NH*HD);
}

// round 5
// speedup vs baseline: 3.6015x; 3.6015x over previous
#include <cuda_runtime.h>
#include <cuda_bf16.h>
#include <cstdint>

// Problem constants
#define BATCH 2
#define LSEQ  2048
#define HID   2048
#define NH    16
#define NKV   8
#define HD    128
#define NIMG  1024
#define MROWS (BATCH*LSEQ)   // 4096

typedef unsigned long long u64;

// ---------------- scratch (device globals; no allocation allowed) ----------
__device__ float g_q [(size_t)BATCH*LSEQ*NH *HD];
__device__ float g_k [(size_t)BATCH*LSEQ*NKV*HD];
__device__ float g_v [(size_t)BATCH*LSEQ*NKV*HD];
__device__ float g_ao[(size_t)BATCH*LSEQ*NH *HD];

// ---------------- f32x2 helpers (Blackwell packed fp32, baseline PTX) ------
__device__ __forceinline__ void ffma2(u64& d, u64 a, u64 b) {
    asm("fma.rn.f32x2 %0, %1, %2, %0;" : "+l"(d) : "l"(a), "l"(b));
}
__device__ __forceinline__ void fmul2(u64& d, u64 a, u64 b) {
    asm("mul.rn.f32x2 %0, %1, %2;" : "=l"(d) : "l"(a), "l"(b));
}
__device__ __forceinline__ u64 pack2(float x, float y) {
    u64 r; asm("mov.b64 %0, {%1, %2};" : "=l"(r) : "f"(x), "f"(y)); return r;
}
__device__ __forceinline__ void unpack2(u64 d, float& x, float& y) {
    asm("mov.b64 {%0, %1}, %2;" : "=f"(x), "=f"(y) : "l"(d));
}

// ---------------- SGEMM via f32x2: C[m,n] = sum_k A[m,k]*B[n,k] ------------
// BM=BN=128, BK=16, 256 threads, 8x8 per thread (acc = 8 x 4 f32x2 pairs).
// Double-buffered smem, transposed tiles As[k][m], Bs[k][n], pad 132.
#define GPAD 132
__global__ __launch_bounds__(256) void sgemm_f32x2(
        const float* __restrict__ A, const float* __restrict__ Bw,
        float* __restrict__ C, int M, int N, int K)
{
    __shared__ float As[2][16][GPAD];
    __shared__ float Bs[2][16][GPAD];

    const int tid = threadIdx.x;
    const int tx  = tid & 15;        // n sub-tile (8 cols)
    const int ty  = tid >> 4;        // m sub-tile (8 rows)
    const int lr  = tid >> 2;        // 0..63 load row
    const int lc  = (tid & 3) * 4;   // 0,4,8,12 load col group

    const float* Ab = A  + (size_t)(blockIdx.y * 128) * K;
    const float* Bb = Bw + (size_t)(blockIdx.x * 128) * K;

    u64 acc[8][4];
#pragma unroll
    for (int i = 0; i < 8; i++)
#pragma unroll
        for (int j = 0; j < 4; j++) acc[i][j] = 0ull;

    const int nch = K / 16;
    float4 ra0, ra1, rb0, rb1;

    // prologue: chunk 0
    ra0 = *(const float4*)(Ab + (size_t)lr * K + lc);
    ra1 = *(const float4*)(Ab + (size_t)(lr + 64) * K + lc);
    rb0 = *(const float4*)(Bb + (size_t)lr * K + lc);
    rb1 = *(const float4*)(Bb + (size_t)(lr + 64) * K + lc);
    {
        float av0[4] = {ra0.x, ra0.y, ra0.z, ra0.w};
        float av1[4] = {ra1.x, ra1.y, ra1.z, ra1.w};
        float bv0[4] = {rb0.x, rb0.y, rb0.z, rb0.w};
        float bv1[4] = {rb1.x, rb1.y, rb1.z, rb1.w};
#pragma unroll
        for (int j = 0; j < 4; j++) {
            As[0][lc + j][lr]      = av0[j];
            As[0][lc + j][lr + 64] = av1[j];
            Bs[0][lc + j][lr]      = bv0[j];
            Bs[0][lc + j][lr + 64] = bv1[j];
        }
    }
    __syncthreads();

    for (int c = 0; c < nch; c++) {
        const int buf = c & 1;
        if (c + 1 < nch) {
            const int k0 = (c + 1) * 16;
            ra0 = *(const float4*)(Ab + (size_t)lr * K + k0 + lc);
            ra1 = *(const float4*)(Ab + (size_t)(lr + 64) * K + k0 + lc);
            rb0 = *(const float4*)(Bb + (size_t)lr * K + k0 + lc);
            rb1 = *(const float4*)(Bb + (size_t)(lr + 64) * K + k0 + lc);
        }

#pragma unroll
        for (int kk = 0; kk < 16; kk++) {
            float4 a0 = *(const float4*)&As[buf][kk][ty * 8];
            float4 a1 = *(const float4*)&As[buf][kk][ty * 8 + 4];
            ulonglong2 b0 = *(const ulonglong2*)&Bs[buf][kk][tx * 8];
            ulonglong2 b1 = *(const ulonglong2*)&Bs[buf][kk][tx * 8 + 4];
            u64 bb[4] = {b0.x, b0.y, b1.x, b1.y};
            float av[8] = {a0.x, a0.y, a0.z, a0.w, a1.x, a1.y, a1.z, a1.w};
#pragma unroll
            for (int i = 0; i < 8; i++) {
                u64 ai = pack2(av[i], av[i]);
#pragma unroll
                for (int j = 0; j < 4; j++) ffma2(acc[i][j], ai, bb[j]);
            }
        }

        if (c + 1 < nch) {
            const int nbuf = buf ^ 1;
            float av0[4] = {ra0.x, ra0.y, ra0.z, ra0.w};
            float av1[4] = {ra1.x, ra1.y, ra1.z, ra1.w};
            float bv0[4] = {rb0.x, rb0.y, rb0.z, rb0.w};
            float bv1[4] = {rb1.x, rb1.y, rb1.z, rb1.w};
#pragma unroll
            for (int j = 0; j < 4; j++) {
                As[nbuf][lc + j][lr]      = av0[j];
                As[nbuf][lc + j][lr + 64] = av1[j];
                Bs[nbuf][lc + j][lr]      = bv0[j];
                Bs[nbuf][lc + j][lr + 64] = bv1[j];
            }
            __syncthreads();
        }
    }

    // epilogue
    const int mBase = blockIdx.y * 128 + ty * 8;
    const int nBase = blockIdx.x * 128 + tx * 8;
#pragma unroll
    for (int i = 0; i < 8; i++) {
        float o[8];
#pragma unroll
        for (int j = 0; j < 4; j++) unpack2(acc[i][j], o[j * 2], o[j * 2 + 1]);
        float* cp = C + (size_t)(mBase + i) * N + nBase;
        *(float4*)(cp)     = make_float4(o[0], o[1], o[2], o[3]);
        *(float4*)(cp + 4) = make_float4(o[4], o[5], o[6], o[7]);
    }
}

// ---------------- fused RMSNorm + RoPE (q and k heads) ---------------------
__global__ __launch_bounds__(128) void rmsnorm_rope_kernel(
        float* __restrict__ qb, float* __restrict__ kb,
        const float* __restrict__ cosb, const float* __restrict__ sinb,
        const float* __restrict__ qw, const float* __restrict__ kw)
{
    const int idx  = blockIdx.x;
    const int head = idx % (NH + NKV);
    const int bl   = idx / (NH + NKV);
    const int d    = threadIdx.x;

    float* vec; const float* w;
    if (head < NH) { vec = qb + ((size_t)bl*NH  + head)      * HD; w = qw; }
    else           { vec = kb + ((size_t)bl*NKV + (head-NH)) * HD; w = kw; }

    float val = vec[d];
    float ss  = val * val;
#pragma unroll
    for (int o = 16; o > 0; o >>= 1) ss += __shfl_xor_sync(0xffffffffu, ss, o);
    __shared__ float wsum[4];
    if ((d & 31) == 0) wsum[d >> 5] = ss;
    __syncthreads();
    float tot = wsum[0] + wsum[1] + wsum[2] + wsum[3];
    float r   = rsqrtf(tot * (1.0f/HD) + 1e-6f);
    float nv  = val * r * w[d];

    __shared__ float sv[HD];
    sv[d] = nv;
    __syncthreads();

    const float* cp = cosb + (size_t)bl * HD;
    const float* sp = sinb + (size_t)bl * HD;
    float outv;
    if (d < 64) outv = nv * cp[d]    - sv[d+64] * sp[d];
    else        outv = nv * cp[d-64] + sv[d-64] * sp[d-64];
    vec[d] = outv;
}

// ---------------- flash attention, fp32 f32x2, hybrid mask -----------------
// 64 queries/block, 128 threads. Each thread: 2 queries (qp, qp+32), 32 dims
// (sub*32..+32). K-tile 32 rows. K frag shared between the 2 queries.
__global__ __launch_bounds__(128) void attn_kernel(
        const float* __restrict__ Q, const float* __restrict__ Kb,
        const float* __restrict__ Vb, float* __restrict__ O)
{
    __shared__ float Ks[32][HD];
    __shared__ float Vs[32][HD];

    const int tid = threadIdx.x;
    const int sub = tid & 3;
    const int qp  = tid >> 2;          // 0..31
    const int b   = blockIdx.z;
    const int h   = blockIdx.y;
    const int q0  = blockIdx.x * 64;
    const int kvh = h >> 1;
    const int qrow0 = q0 + qp;
    const int qrow1 = q0 + qp + 32;

    u64 q2[2][16];
#pragma unroll
    for (int e = 0; e < 2; e++) {
        const int qr = (e == 0) ? qrow0 : qrow1;
        const ulonglong2* qp4 = (const ulonglong2*)(Q + (((size_t)b*LSEQ + qr)*NH + h)*HD + sub*32);
#pragma unroll
        for (int j = 0; j < 8; j++) {
            ulonglong2 v = qp4[j];
            q2[e][j*2]   = v.x;
            q2[e][j*2+1] = v.y;
        }
    }

    float m0 = -1e30f, m1 = -1e30f, l0 = 0.f, l1 = 0.f;
    u64 acc[2][16];
#pragma unroll
    for (int e = 0; e < 2; e++)
#pragma unroll
        for (int j = 0; j < 16; j++) acc[e][j] = 0ull;

    const float scale = 0.08838834764831844f;   // 1/sqrt(128)
    const int nk = (q0 >= NIMG) ? (q0/32 + 2) : (LSEQ/32);
    const bool img = (q0 < NIMG);

    for (int t = 0; t < nk; t++) {
        const int k0 = t * 32;
        const size_t kbase = (((size_t)b*LSEQ + k0)*NKV + kvh)*HD;
#pragma unroll
        for (int i = 0; i < 8; i++) {
            int idx = tid + i*128;          // 0..1023
            int row = idx >> 5, c = (idx & 31) << 2;
            size_t g = kbase + (size_t)row*NKV*HD + c;
            *(float4*)&Ks[row][c] = *(const float4*)(Kb + g);
            *(float4*)&Vs[row][c] = *(const float4*)(Vb + g);
        }
        __syncthreads();

        float sloc0[8], sloc1[8];
        float smax0 = -1e30f, smax1 = -1e30f;
#pragma unroll
        for (int kk = 0; kk < 32; kk++) {
            const ulonglong2* kr = (const ulonglong2*)&Ks[kk][sub*32];
            u64 p20 = 0ull, p21 = 0ull;
#pragma unroll
            for (int j = 0; j < 8; j++) {
                ulonglong2 kv = kr[j];
                ffma2(p20, q2[0][j*2],   kv.x);
                ffma2(p21, q2[1][j*2],   kv.x);
                ffma2(p20, q2[0][j*2+1], kv.y);
                ffma2(p21, q2[1][j*2+1], kv.y);
            }
            float x0, y0, x1, y1;
            unpack2(p20, x0, y0); unpack2(p21, x1, y1);
            float p0 = x0 + y0, p1 = x1 + y1;
            p0 += __shfl_xor_sync(0xffffffffu, p0, 1);
            p0 += __shfl_xor_sync(0xffffffffu, p0, 2);
            p1 += __shfl_xor_sync(0xffffffffu, p1, 1);
            p1 += __shfl_xor_sync(0xffffffffu, p1, 2);
            p0 *= scale; p1 *= scale;
            const int kc = k0 + kk;
            if (!img) {
                if (kc > qrow0) p0 = -1e30f;
                if (kc > qrow1) p1 = -1e30f;
            }
            if ((kk & 3) == sub) { sloc0[kk >> 2] = p0; sloc1[kk >> 2] = p1; }
            smax0 = fmaxf(smax0, p0);
            smax1 = fmaxf(smax1, p1);
        }

        const float newm0 = fmaxf(m0, smax0);
        const float newm1 = fmaxf(m1, smax1);
        const float a0 = __expf(fmaxf(m0 - newm0, -80.f));
        const float a1 = __expf(fmaxf(m1 - newm1, -80.f));
        l0 *= a0; l1 *= a1;
        {
            u64 pa0 = pack2(a0, a0), pa1 = pack2(a1, a1);
#pragma unroll
            for (int j = 0; j < 16; j++) {
                fmul2(acc[0][j], acc[0][j], pa0);
                fmul2(acc[1][j], acc[1][j], pa1);
            }
        }

#pragma unroll
        for (int kk = 0; kk < 32; kk++) {
            float s0 = __shfl_sync(0xffffffffu, sloc0[kk >> 2], kk & 3, 4);
            float s1 = __shfl_sync(0xffffffffu, sloc1[kk >> 2], kk & 3, 4);
            float e0 = __expf(fmaxf(s0 - newm0, -80.f));
            float e1 = __expf(fmaxf(s1 - newm1, -80.f));
            l0 += e0; l1 += e1;
            u64 pe0 = pack2(e0, e0), pe1 = pack2(e1, e1);
            const ulonglong2* vr = (const ulonglong2*)&Vs[kk][sub*32];
#pragma unroll
            for (int j = 0; j < 8; j++) {
                ulonglong2 vv = vr[j];
                ffma2(acc[0][j*2],   pe0, vv.x);
                ffma2(acc[1][j*2],   pe1, vv.x);
                ffma2(acc[0][j*2+1], pe0, vv.y);
                ffma2(acc[1][j*2+1], pe1, vv.y);
            }
        }
        m0 = newm0; m1 = newm1;
        __syncthreads();
    }

    const float inv0 = 1.f / l0;
    const float inv1 = 1.f / l1;
#pragma unroll
    for (int e = 0; e < 2; e++) {
        const int qr = (e == 0) ? qrow0 : qrow1;
        const float inv = (e == 0) ? inv0 : inv1;
        float* op = O + (((size_t)b*LSEQ + qr)*NH + h)*HD + sub*32;
#pragma unroll
        for (int j = 0; j < 8; j++) {
            float x, y;
            unpack2(acc[e][j*2], x, y);
            float zx, zy;
            unpack2(acc[e][j*2+1], zx, zy);
            *(float4*)(op + j*4) = make_float4(x*inv, y*inv, zx*inv, zy*inv);
        }
    }
}

// ---------------- launch ----------------------------------------------------
extern "C" void kernel_launch(void* const* d_in, const int* in_sizes, int n_in,
                              void* d_out, int out_size)
{
    const float* x    = (const float*)d_in[0];
    const float* cosb = (const float*)d_in[1];
    const float* sinb = (const float*)d_in[2];
    // d_in[3] = attention_mask (recomputed analytically, unused)
    const float* Wq   = (const float*)d_in[4];
    const float* Wk   = (const float*)d_in[5];
    const float* Wv   = (const float*)d_in[6];
    const float* Wo   = (const float*)d_in[7];
    const float* qw   = (const float*)d_in[8];
    const float* kw   = (const float*)d_in[9];
    float* out = (float*)d_out;

    float *gq, *gk, *gv, *gao;
    cudaGetSymbolAddress((void**)&gq,  g_q);
    cudaGetSymbolAddress((void**)&gk,  g_k);
    cudaGetSymbolAddress((void**)&gv,  g_v);
    cudaGetSymbolAddress((void**)&gao, g_ao);

    // QKV projections (f32x2 SGEMM)
    sgemm_f32x2<<<dim3(NH*HD/128,  MROWS/128), 256>>>(x, Wq, gq, MROWS, NH*HD,  HID);
    sgemm_f32x2<<<dim3(NKV*HD/128, MROWS/128), 256>>>(x, Wk, gk, MROWS, NKV*HD, HID);
    sgemm_f32x2<<<dim3(NKV*HD/128, MROWS/128), 256>>>(x, Wv, gv, MROWS, NKV*HD, HID);

    // RMSNorm + RoPE
    rmsnorm_rope_kernel<<<BATCH*LSEQ*(NH+NKV), 128>>>(gq, gk, cosb, sinb, qw, kw);

    // Attention
    attn_kernel<<<dim3(LSEQ/64, NH, BATCH), 128>>>(gq, gk, gv, gao);

    // Output projection
    sgemm_f32x2<<<dim3(HID/128, MROWS/128), 256>>>(gao, Wo, out, MROWS, HID, NH*HD);
}